// round 14
// baseline (speedup 1.0000x reference)
#include <cuda_runtime.h>
#include <cuda_bf16.h>
#include <mma.h>
#include <cstdint>

using namespace nvcuda;

#define NROWS 32768
#define KDIM  512
#define NQKV  1536
#define NINST 8192

// ---------------- device scratch (referenced ONLY in device code) ----------
__device__ __align__(16) float          g_qkv[(size_t)NROWS * NQKV];
__device__ __align__(16) unsigned short g_xnhi[(size_t)NROWS * KDIM];
__device__ __align__(16) unsigned short g_xnlo[(size_t)NROWS * KDIM];
__device__ __align__(16) unsigned short g_vhhi[(size_t)NROWS * KDIM];
__device__ __align__(16) unsigned short g_vhlo[(size_t)NROWS * KDIM];
__device__ __align__(16) unsigned short g_wqhi[(size_t)NQKV * KDIM];   // W_qkv^T [N][K]
__device__ __align__(16) unsigned short g_wqlo[(size_t)NQKV * KDIM];
__device__ __align__(16) unsigned short g_wohi[(size_t)KDIM * KDIM];   // W_out^T [N][K]
__device__ __align__(16) unsigned short g_wolo[(size_t)KDIM * KDIM];

__device__ __forceinline__ void bfsplit(float v, unsigned short& hi, unsigned short& lo) {
    __nv_bfloat16 h = __float2bfloat16(v);
    float r = v - __bfloat162float(h);
    __nv_bfloat16 l = __float2bfloat16(r);
    hi = __bfloat16_as_ushort(h);
    lo = __bfloat16_as_ushort(l);
}

__device__ __forceinline__ uint32_t smem_u32(const void* p) {
    uint32_t a;
    asm("{ .reg .u64 t; cvta.to.shared.u64 t, %1; cvt.u32.u64 %0, t; }" : "=r"(a) : "l"(p));
    return a;
}
__device__ __forceinline__ void cp16(uint32_t saddr, const void* g) {
    asm volatile("cp.async.cg.shared.global [%0], [%1], 16;" :: "r"(saddr), "l"(g));
}

// ---------------------------------------------------------------------------
// LayerNorm: one warp per row; writes bf16 hi/lo splits.
// ---------------------------------------------------------------------------
__global__ __launch_bounds__(256) void ln_kernel(const float* __restrict__ x,
                                                 const float* __restrict__ gamma,
                                                 const float* __restrict__ beta)
{
    int row  = (blockIdx.x * 256 + threadIdx.x) >> 5;
    int lane = threadIdx.x & 31;

    const float4* xr = (const float4*)(x + (size_t)row * KDIM);
    float4 v[4];
    float s = 0.f, ss = 0.f;
#pragma unroll
    for (int i = 0; i < 4; i++) {
        v[i] = xr[lane + i * 32];
        s  += v[i].x + v[i].y + v[i].z + v[i].w;
        ss += v[i].x * v[i].x + v[i].y * v[i].y + v[i].z * v[i].z + v[i].w * v[i].w;
    }
#pragma unroll
    for (int o = 16; o; o >>= 1) {
        s  += __shfl_xor_sync(0xffffffffu, s, o);
        ss += __shfl_xor_sync(0xffffffffu, ss, o);
    }
    float mean = s * (1.0f / KDIM);
    float inv  = rsqrtf(ss * (1.0f / KDIM) - mean * mean + 1e-5f);

    const float4* g4 = (const float4*)gamma;
    const float4* b4 = (const float4*)beta;
#pragma unroll
    for (int i = 0; i < 4; i++) {
        int idx = lane + i * 32;
        float4 g = g4[idx], b = b4[idx], r;
        r.x = (v[i].x - mean) * inv * g.x + b.x;
        r.y = (v[i].y - mean) * inv * g.y + b.y;
        r.z = (v[i].z - mean) * inv * g.z + b.z;
        r.w = (v[i].w - mean) * inv * g.w + b.w;
        __align__(8) unsigned short h4[4], l4[4];
        bfsplit(r.x, h4[0], l4[0]); bfsplit(r.y, h4[1], l4[1]);
        bfsplit(r.z, h4[2], l4[2]); bfsplit(r.w, h4[3], l4[3]);
        size_t e = (size_t)row * KDIM + idx * 4;
        *(uint2*)(g_xnhi + e) = *(uint2*)h4;
        *(uint2*)(g_xnlo + e) = *(uint2*)l4;
    }
}

// ---------------------------------------------------------------------------
// Weight transpose + split: W[K][N] fp32 -> T_hi/lo[N][K] bf16.
// ---------------------------------------------------------------------------
template<bool ISQKV>
__global__ __launch_bounds__(256) void wsplit_kernel(const float* __restrict__ W)
{
    unsigned short* Thi = ISQKV ? g_wqhi : g_wohi;
    unsigned short* Tlo = ISQKV ? g_wqlo : g_wolo;
    const int N = ISQKV ? NQKV : KDIM;

    __shared__ float t[32][33];
    int x = blockIdx.x * 32, y = blockIdx.y * 32;
    int tx = threadIdx.x & 31, ty = threadIdx.x >> 5;
#pragma unroll
    for (int j = 0; j < 4; j++)
        t[ty + 8 * j][tx] = W[(size_t)(y + ty + 8 * j) * N + x + tx];
    __syncthreads();
#pragma unroll
    for (int j = 0; j < 4; j++) {
        float v = t[tx][ty + 8 * j];
        int n = x + ty + 8 * j, k = y + tx;
        unsigned short hi, lo;
        bfsplit(v, hi, lo);
        Thi[(size_t)n * KDIM + k] = hi;
        Tlo[(size_t)n * KDIM + k] = lo;
    }
}

// ---------------------------------------------------------------------------
// WMMA bf16 split GEMM, 512 threads, 3-STAGE cp.async ring, ONE sync/K-step.
// (R13: two barriers per step gated 16 warps twice per chunk; with 3 buffers
// the tile issued at kt (for kt+2) reuses the buffer read at kt-1, and the
// top-of-loop barrier already proves compute(kt-1) finished everywhere.)
// Block tile 128x128, BK=32, warp grid 4x4, warp tile 32x32.
// smem stride 40 bf16 = 80B: conflict-free LDSM. 3 bufs x 40KB = 120KB.
// ---------------------------------------------------------------------------
template<bool ISQKV>
__global__ __launch_bounds__(512) void wmma_gemm_kernel(float* __restrict__ Cout)
{
    extern __shared__ __align__(16) __nv_bfloat16 sdyn[];
    // per-buffer layout (elements): base = buf*20480;
    //   Ahi=+0, Alo=+5120, Bhi=+10240, Blo=+15360 (each 128 rows x 40 stride)

    const int N = ISQKV ? NQKV : KDIM;
    const unsigned short* pA[2] = { ISQKV ? g_xnhi : g_vhhi, ISQKV ? g_xnlo : g_vhlo };
    const unsigned short* pB[2] = { ISQKV ? g_wqhi : g_wohi, ISQKV ? g_wqlo : g_wolo };
    float* C = ISQKV ? g_qkv : Cout;

    const int tid = threadIdx.x, wid = tid >> 5;
    const int wm = wid >> 2;            // 0..3 -> m offset 32*wm
    const int wn = wid & 3;             // 0..3 -> n offset 32*wn
    const int m0 = blockIdx.y * 128, n0 = blockIdx.x * 128;
    const uint32_t sb = smem_u32(sdyn);

    wmma::fragment<wmma::accumulator, 16, 16, 16, float> acc[2][2];
#pragma unroll
    for (int i = 0; i < 2; i++)
#pragma unroll
        for (int j = 0; j < 2; j++) wmma::fill_fragment(acc[i][j], 0.0f);

    // 2048 16B-chunks per tile (A: 1024 = 2 splits x 128 rows x 4; B same);
    // 512 threads x 4 chunks.
#define ISSUE_TILE(KT, BUF) do { \
    const int _k0 = (KT) * 32; \
    _Pragma("unroll") \
    for (int t = 0; t < 4; t++) { \
        int cid = tid + t * 512; \
        int isB = cid >= 1024; \
        int c   = isB ? cid - 1024 : cid; \
        int s   = c >> 9; \
        int r   = (c >> 2) & 127; \
        int kc  = c & 3; \
        const unsigned short* src = isB ? pB[s] : pA[s]; \
        int b0 = isB ? n0 : m0; \
        uint32_t dst = sb + (uint32_t)((((BUF) * 20480) + (isB ? 10240 : 0) + s * 5120 + r * 40 + kc * 8) * 2); \
        cp16(dst, src + (size_t)(b0 + r) * KDIM + _k0 + kc * 8); \
    } \
    asm volatile("cp.async.commit_group;"); \
} while (0)

    ISSUE_TILE(0, 0);
    ISSUE_TILE(1, 1);

#pragma unroll 1
    for (int kt = 0; kt < 16; kt++) {
        const int buf = kt % 3;
        if (kt < 15) asm volatile("cp.async.wait_group 1;" ::: "memory");
        else         asm volatile("cp.async.wait_group 0;" ::: "memory");
        __syncthreads();                       // tile kt visible; buf (kt+2)%3 free
        if (kt + 2 < 16) ISSUE_TILE(kt + 2, (kt + 2) % 3);

        const __nv_bfloat16* cAh = sdyn + buf * 20480;
        const __nv_bfloat16* cAl = cAh + 5120;
        const __nv_bfloat16* cBh = cAh + 10240;
        const __nv_bfloat16* cBl = cAh + 15360;

#pragma unroll
        for (int ks = 0; ks < 2; ks++) {
            wmma::fragment<wmma::matrix_a, 16, 16, 16, __nv_bfloat16, wmma::row_major> ah[2], al[2];
            wmma::fragment<wmma::matrix_b, 16, 16, 16, __nv_bfloat16, wmma::col_major> bh[2], bl[2];
#pragma unroll
            for (int tm = 0; tm < 2; tm++) {
                wmma::load_matrix_sync(ah[tm], cAh + (wm * 32 + tm * 16) * 40 + ks * 16, 40);
                wmma::load_matrix_sync(al[tm], cAl + (wm * 32 + tm * 16) * 40 + ks * 16, 40);
            }
#pragma unroll
            for (int tn = 0; tn < 2; tn++) {
                wmma::load_matrix_sync(bh[tn], cBh + (wn * 32 + tn * 16) * 40 + ks * 16, 40);
                wmma::load_matrix_sync(bl[tn], cBl + (wn * 32 + tn * 16) * 40 + ks * 16, 40);
            }
#pragma unroll
            for (int tm = 0; tm < 2; tm++)
#pragma unroll
                for (int tn = 0; tn < 2; tn++) {
                    wmma::mma_sync(acc[tm][tn], ah[tm], bh[tn], acc[tm][tn]);
                    wmma::mma_sync(acc[tm][tn], ah[tm], bl[tn], acc[tm][tn]);
                    wmma::mma_sync(acc[tm][tn], al[tm], bh[tn], acc[tm][tn]);
                }
        }
    }

#pragma unroll
    for (int tm = 0; tm < 2; tm++)
#pragma unroll
        for (int tn = 0; tn < 2; tn++)
            wmma::store_matrix_sync(C + (size_t)(m0 + wm * 32 + tm * 16) * N + n0 + wn * 32 + tn * 16,
                                    acc[tm][tn], N, wmma::mem_row_major);
#undef ISSUE_TILE
}

// ---------------------------------------------------------------------------
// Bias add on out (fp32, [NROWS][512])
// ---------------------------------------------------------------------------
__global__ __launch_bounds__(256) void bias_add_kernel(float* __restrict__ out,
                                                       const float* __restrict__ bias)
{
    size_t i = (size_t)blockIdx.x * 256 + threadIdx.x;     // float4 index
    float4 v = ((const float4*)out)[i];
    const float4 b = *(const float4*)(bias + (int)((i & 127) * 4));
    v.x += b.x; v.y += b.y; v.z += b.z; v.w += b.w;
    ((float4*)out)[i] = v;
}

// ---------------------------------------------------------------------------
// Attention: one block per instance (8192). Conflict-free smem layout.
// QK loop now loads q as float4 (16 LDS vs 64 scalar): 80 LDS/thread total.
// ---------------------------------------------------------------------------
__global__ __launch_bounds__(256) void attn_kernel()
{
    __shared__ float sQ[32][68];
    __shared__ float sKT[64][36];
    __shared__ float sV[32][68];
    __shared__ float S[32 * 33];

    const int inst = blockIdx.x;
    const int d2 = inst & 15;
    const int c2 = (inst >> 4) & 15;
    const int h  = (inst >> 8) & 7;
    const int b  = inst >> 11;
    const int c  = 2 * h + (c2 >> 3);
    const int d  = 2 * (c2 & 7) + (d2 >> 3);
    const int wb = 4 * (d2 & 7);
    const size_t rowIdx  = (((size_t)(b * 16 + c) * 16 + d) * 32 + wb);
    const size_t srcBase = rowIdx * 1536;
    const size_t dstBase = rowIdx * 512;

    const int tid = threadIdx.x;
    const float4* src4 = (const float4*)(g_qkv + srcBase);

#pragma unroll
    for (int it = 0; it < 6; it++) {
        int p = tid + it * 256;
        float4 v = src4[p];
        int r  = p / 384;
        int f  = p - r * 384;
        int o  = f / 48;
        int t4 = f - o * 48;
        int sec = t4 >> 4;         // 0=Q 1=K 2=V
        int e   = (t4 & 15) * 4;
        int w2  = r * 8 + o;
        if (sec == 0)      *(float4*)&sQ[w2][e] = v;
        else if (sec == 2) *(float4*)&sV[w2][e] = v;
        else {
            sKT[e + 0][w2] = v.x;
            sKT[e + 1][w2] = v.y;
            sKT[e + 2][w2] = v.z;
            sKT[e + 3][w2] = v.w;
        }
    }
    __syncthreads();

    {
        const int i  = tid >> 3;
        const int jg = (tid & 7) * 4;
        const float* qr = sQ[i];
        float s0 = 0.f, s1 = 0.f, s2 = 0.f, s3 = 0.f;
#pragma unroll
        for (int e4 = 0; e4 < 64; e4 += 4) {
            float4 q4 = *(const float4*)(qr + e4);
            float4 ka = *(const float4*)&sKT[e4 + 0][jg];
            float4 kb = *(const float4*)&sKT[e4 + 1][jg];
            float4 kc = *(const float4*)&sKT[e4 + 2][jg];
            float4 kd = *(const float4*)&sKT[e4 + 3][jg];
            s0 = fmaf(q4.x, ka.x, s0); s1 = fmaf(q4.x, ka.y, s1);
            s2 = fmaf(q4.x, ka.z, s2); s3 = fmaf(q4.x, ka.w, s3);
            s0 = fmaf(q4.y, kb.x, s0); s1 = fmaf(q4.y, kb.y, s1);
            s2 = fmaf(q4.y, kb.z, s2); s3 = fmaf(q4.y, kb.w, s3);
            s0 = fmaf(q4.z, kc.x, s0); s1 = fmaf(q4.z, kc.y, s1);
            s2 = fmaf(q4.z, kc.z, s2); s3 = fmaf(q4.z, kc.w, s3);
            s0 = fmaf(q4.w, kd.x, s0); s1 = fmaf(q4.w, kd.y, s1);
            s2 = fmaf(q4.w, kd.z, s2); s3 = fmaf(q4.w, kd.w, s3);
        }
        S[i * 33 + jg + 0] = s0 * 8.0f;
        S[i * 33 + jg + 1] = s1 * 8.0f;
        S[i * 33 + jg + 2] = s2 * 8.0f;
        S[i * 33 + jg + 3] = s3 * 8.0f;
    }
    __syncthreads();

    {
        const int warp = tid >> 5, lane = tid & 31;
#pragma unroll
        for (int r = 0; r < 4; r++) {
            int i = warp * 4 + r;
            float v = S[i * 33 + lane];
            float m = v;
#pragma unroll
            for (int o = 16; o; o >>= 1) m = fmaxf(m, __shfl_xor_sync(0xffffffffu, m, o));
            float p = __expf(v - m);
            float s = p;
#pragma unroll
            for (int o = 16; o; o >>= 1) s += __shfl_xor_sync(0xffffffffu, s, o);
            S[i * 33 + lane] = p * __frcp_rn(s);
        }
    }
    __syncthreads();

    {
        const int i  = tid >> 3;
        const int eg = (tid & 7) * 8;
        float acc[8] = {0.f,0.f,0.f,0.f,0.f,0.f,0.f,0.f};
#pragma unroll
        for (int j = 0; j < 32; j++) {
            float a = S[i * 33 + j];
            float4 v0 = *(const float4*)&sV[j][eg];
            float4 v1 = *(const float4*)&sV[j][eg + 4];
            acc[0] += a*v0.x; acc[1] += a*v0.y; acc[2] += a*v0.z; acc[3] += a*v0.w;
            acc[4] += a*v1.x; acc[5] += a*v1.y; acc[6] += a*v1.z; acc[7] += a*v1.w;
        }
        __align__(16) unsigned short h8[8], l8[8];
#pragma unroll
        for (int q = 0; q < 8; q++) bfsplit(acc[q], h8[q], l8[q]);
        size_t o = dstBase + (size_t)(i >> 3) * 512 + (i & 7) * 64 + eg;
        *(uint4*)(g_vhhi + o) = *(uint4*)h8;
        *(uint4*)(g_vhlo + o) = *(uint4*)l8;
    }
}

// ---------------------------------------------------------------------------
extern "C" void kernel_launch(void* const* d_in, const int* in_sizes, int n_in,
                              void* d_out, int out_size)
{
    if (n_in < 6) return;
    int used[32];
    for (int i = 0; i < 32; i++) used[i] = 0;
    int big[3] = {-1, -1, -1};
    for (int r = 0; r < 3; r++) {
        int best = -1; long long bs = -1;
        for (int i = 0; i < n_in && i < 32; i++) {
            if (used[i]) continue;
            if ((long long)in_sizes[i] > bs) { bs = (long long)in_sizes[i]; best = i; }
        }
        if (best < 0) return;
        big[r] = best; used[best] = 1;
    }
    const float* x     = (const float*)d_in[big[0]];
    const float* W_qkv = (const float*)d_in[big[1]];
    const float* W_out = (const float*)d_in[big[2]];
    const float* vecs[3] = {nullptr, nullptr, nullptr};
    int nv = 0;
    for (int i = 0; i < n_in && i < 32; i++)
        if (!used[i] && nv < 3) vecs[nv++] = (const float*)d_in[i];
    if (nv < 3 || !x || !W_qkv || !W_out) return;

    const float* gamma = vecs[0];
    const float* beta  = vecs[1];
    const float* b_out = vecs[2];
    float* out = (float*)d_out;

    const int GSM = 122880;   // 3 buffers x 40KB
    cudaFuncSetAttribute(wmma_gemm_kernel<true>,  cudaFuncAttributeMaxDynamicSharedMemorySize, GSM);
    cudaFuncSetAttribute(wmma_gemm_kernel<false>, cudaFuncAttributeMaxDynamicSharedMemorySize, GSM);

    ln_kernel<<<NROWS / 8, 256>>>(x, gamma, beta);
    wsplit_kernel<true><<<dim3(NQKV / 32, KDIM / 32), 256>>>(W_qkv);
    wsplit_kernel<false><<<dim3(KDIM / 32, KDIM / 32), 256>>>(W_out);
    wmma_gemm_kernel<true><<<dim3(NQKV / 128, NROWS / 128), 512, GSM>>>(nullptr);
    attn_kernel<<<NINST, 256>>>();
    wmma_gemm_kernel<false><<<dim3(KDIM / 128, NROWS / 128), 512, GSM>>>(out);
    bias_add_kernel<<<NROWS * KDIM / 4 / 256, 256>>>(out, b_out);
}

// round 15
// speedup vs baseline: 1.0374x; 1.0374x over previous
#include <cuda_runtime.h>
#include <cuda_bf16.h>
#include <mma.h>
#include <cstdint>

using namespace nvcuda;

#define NROWS 32768
#define KDIM  512
#define NQKV  1536
#define NINST 8192

// ---------------- device scratch (referenced ONLY in device code) ----------
__device__ __align__(16) float          g_qkv[(size_t)NROWS * NQKV];
__device__ __align__(16) unsigned short g_xnhi[(size_t)NROWS * KDIM];
__device__ __align__(16) unsigned short g_xnlo[(size_t)NROWS * KDIM];
__device__ __align__(16) unsigned short g_vhhi[(size_t)NROWS * KDIM];
__device__ __align__(16) unsigned short g_vhlo[(size_t)NROWS * KDIM];
__device__ __align__(16) unsigned short g_wqhi[(size_t)NQKV * KDIM];   // W_qkv^T [N][K]
__device__ __align__(16) unsigned short g_wqlo[(size_t)NQKV * KDIM];
__device__ __align__(16) unsigned short g_wohi[(size_t)KDIM * KDIM];   // W_out^T [N][K]
__device__ __align__(16) unsigned short g_wolo[(size_t)KDIM * KDIM];

__device__ __forceinline__ void bfsplit(float v, unsigned short& hi, unsigned short& lo) {
    __nv_bfloat16 h = __float2bfloat16(v);
    float r = v - __bfloat162float(h);
    __nv_bfloat16 l = __float2bfloat16(r);
    hi = __bfloat16_as_ushort(h);
    lo = __bfloat16_as_ushort(l);
}

__device__ __forceinline__ uint32_t smem_u32(const void* p) {
    uint32_t a;
    asm("{ .reg .u64 t; cvta.to.shared.u64 t, %1; cvt.u32.u64 %0, t; }" : "=r"(a) : "l"(p));
    return a;
}
__device__ __forceinline__ void cp16(uint32_t saddr, const void* g) {
    asm volatile("cp.async.cg.shared.global [%0], [%1], 16;" :: "r"(saddr), "l"(g));
}

// ---------------------------------------------------------------------------
// Prep kernel: LN (blocks 0..4095) + W_qkv split (4096..4863) + W_out split
// (4864..5119). Independent outputs; merged to kill inter-launch serialization.
// ---------------------------------------------------------------------------
__global__ __launch_bounds__(256) void prep_kernel(const float* __restrict__ x,
                                                   const float* __restrict__ gamma,
                                                   const float* __restrict__ beta,
                                                   const float* __restrict__ Wq,
                                                   const float* __restrict__ Wo)
{
    __shared__ float t[32][33];
    const int nb = blockIdx.x;

    if (nb < 4096) {
        // ---- LayerNorm: one warp per row ----
        int row  = (nb * 256 + threadIdx.x) >> 5;
        int lane = threadIdx.x & 31;

        const float4* xr = (const float4*)(x + (size_t)row * KDIM);
        float4 v[4];
        float s = 0.f, ss = 0.f;
#pragma unroll
        for (int i = 0; i < 4; i++) {
            v[i] = xr[lane + i * 32];
            s  += v[i].x + v[i].y + v[i].z + v[i].w;
            ss += v[i].x * v[i].x + v[i].y * v[i].y + v[i].z * v[i].z + v[i].w * v[i].w;
        }
#pragma unroll
        for (int o = 16; o; o >>= 1) {
            s  += __shfl_xor_sync(0xffffffffu, s, o);
            ss += __shfl_xor_sync(0xffffffffu, ss, o);
        }
        float mean = s * (1.0f / KDIM);
        float inv  = rsqrtf(ss * (1.0f / KDIM) - mean * mean + 1e-5f);

        const float4* g4 = (const float4*)gamma;
        const float4* b4 = (const float4*)beta;
#pragma unroll
        for (int i = 0; i < 4; i++) {
            int idx = lane + i * 32;
            float4 g = g4[idx], b = b4[idx], r;
            r.x = (v[i].x - mean) * inv * g.x + b.x;
            r.y = (v[i].y - mean) * inv * g.y + b.y;
            r.z = (v[i].z - mean) * inv * g.z + b.z;
            r.w = (v[i].w - mean) * inv * g.w + b.w;
            __align__(8) unsigned short h4[4], l4[4];
            bfsplit(r.x, h4[0], l4[0]); bfsplit(r.y, h4[1], l4[1]);
            bfsplit(r.z, h4[2], l4[2]); bfsplit(r.w, h4[3], l4[3]);
            size_t e = (size_t)row * KDIM + idx * 4;
            *(uint2*)(g_xnhi + e) = *(uint2*)h4;
            *(uint2*)(g_xnlo + e) = *(uint2*)l4;
        }
    } else {
        // ---- weight transpose + split ----
        const bool isq = nb < 4864;
        const int tix  = isq ? (nb - 4096) : (nb - 4864);
        const int NBX  = isq ? 48 : 16;
        const int bx = tix % NBX, by = tix / NBX;
        const float* W = isq ? Wq : Wo;
        unsigned short* Thi = isq ? g_wqhi : g_wohi;
        unsigned short* Tlo = isq ? g_wqlo : g_wolo;
        const int N = isq ? NQKV : KDIM;

        int xo = bx * 32, yo = by * 32;
        int tx = threadIdx.x & 31, ty = threadIdx.x >> 5;
#pragma unroll
        for (int j = 0; j < 4; j++)
            t[ty + 8 * j][tx] = W[(size_t)(yo + ty + 8 * j) * N + xo + tx];
        __syncthreads();
#pragma unroll
        for (int j = 0; j < 4; j++) {
            float v = t[tx][ty + 8 * j];
            int n = xo + ty + 8 * j, k = yo + tx;
            unsigned short hi, lo;
            bfsplit(v, hi, lo);
            Thi[(size_t)n * KDIM + k] = hi;
            Tlo[(size_t)n * KDIM + k] = lo;
        }
    }
}

// ---------------------------------------------------------------------------
// WMMA bf16 split GEMM. R14 post-mortem: intra-CTA pipelining plateaued at
// tensor~44% because ONE CTA/SM leaves barrier gaps unfilled. New shape:
// block tile 128x64, 256 threads (8 warps, 4x2, warp tile 32x32), 2-stage
// cp.async, smem 60KB -> TWO CTAs/SM fill each other's barrier/drain gaps.
// smem stride 40 bf16 = 80B: conflict-free LDSM.
// !ISQKV fuses the bias add via smem staging (deletes bias_add pass).
// ---------------------------------------------------------------------------
template<bool ISQKV>
__global__ __launch_bounds__(256, 2) void wmma_gemm_kernel(const float* __restrict__ bias,
                                                           float* __restrict__ Cout)
{
    extern __shared__ __align__(16) __nv_bfloat16 sdyn[];
    // stage base (elements) = stg*15360:
    //   Ahi +0 (128x40), Alo +5120, Bhi +10240 (64x40), Blo +12800
    // total 2 stages x 15360 el = 61440 B

    const int N = ISQKV ? NQKV : KDIM;
    const unsigned short* pA[2] = { ISQKV ? g_xnhi : g_vhhi, ISQKV ? g_xnlo : g_vhlo };
    const unsigned short* pB[2] = { ISQKV ? g_wqhi : g_wohi, ISQKV ? g_wqlo : g_wolo };
    float* C = ISQKV ? g_qkv : Cout;

    const int tid = threadIdx.x, wid = tid >> 5, lane = tid & 31;
    const int wm = wid >> 1;            // 0..3 -> m offset 32*wm
    const int wn = wid & 1;             // 0..1 -> n offset 32*wn
    const int m0 = blockIdx.y * 128, n0 = blockIdx.x * 64;
    const uint32_t sb = smem_u32(sdyn);

    wmma::fragment<wmma::accumulator, 16, 16, 16, float> acc[2][2];
#pragma unroll
    for (int i = 0; i < 2; i++)
#pragma unroll
        for (int j = 0; j < 2; j++) wmma::fill_fragment(acc[i][j], 0.0f);

    // 1536 16B-chunks per stage: A = 2 splits x 128 rows x 4 = 1024,
    // B = 2 x 64 x 4 = 512. 256 threads x 6 chunks.
#define ISSUE_TILE(KT, STG) do { \
    const int _k0 = (KT) * 32; \
    _Pragma("unroll") \
    for (int t = 0; t < 6; t++) { \
        int cid = tid + t * 256; \
        if (cid < 1024) { \
            int s = cid >> 9, r = (cid >> 2) & 127, kc = cid & 3; \
            uint32_t dst = sb + (uint32_t)(((STG) * 15360 + s * 5120 + r * 40 + kc * 8) * 2); \
            cp16(dst, pA[s] + (size_t)(m0 + r) * KDIM + _k0 + kc * 8); \
        } else { \
            int c = cid - 1024; \
            int s = c >> 8, r = (c >> 2) & 63, kc = c & 3; \
            uint32_t dst = sb + (uint32_t)(((STG) * 15360 + 10240 + s * 2560 + r * 40 + kc * 8) * 2); \
            cp16(dst, pB[s] + (size_t)(n0 + r) * KDIM + _k0 + kc * 8); \
        } \
    } \
    asm volatile("cp.async.commit_group;"); \
} while (0)

    ISSUE_TILE(0, 0);

#pragma unroll 1
    for (int kt = 0; kt < 16; kt++) {
        const int stg = kt & 1;
        const bool hasNext = (kt < 15);
        if (hasNext) ISSUE_TILE(kt + 1, stg ^ 1);
        if (hasNext) asm volatile("cp.async.wait_group 1;" ::: "memory");
        else         asm volatile("cp.async.wait_group 0;" ::: "memory");
        __syncthreads();

        const __nv_bfloat16* cAh = sdyn + stg * 15360;
        const __nv_bfloat16* cAl = cAh + 5120;
        const __nv_bfloat16* cBh = cAh + 10240;
        const __nv_bfloat16* cBl = cAh + 12800;

#pragma unroll
        for (int ks = 0; ks < 2; ks++) {
            wmma::fragment<wmma::matrix_a, 16, 16, 16, __nv_bfloat16, wmma::row_major> ah[2], al[2];
            wmma::fragment<wmma::matrix_b, 16, 16, 16, __nv_bfloat16, wmma::col_major> bh[2], bl[2];
#pragma unroll
            for (int tm = 0; tm < 2; tm++) {
                wmma::load_matrix_sync(ah[tm], cAh + (wm * 32 + tm * 16) * 40 + ks * 16, 40);
                wmma::load_matrix_sync(al[tm], cAl + (wm * 32 + tm * 16) * 40 + ks * 16, 40);
            }
#pragma unroll
            for (int tn = 0; tn < 2; tn++) {
                wmma::load_matrix_sync(bh[tn], cBh + (wn * 32 + tn * 16) * 40 + ks * 16, 40);
                wmma::load_matrix_sync(bl[tn], cBl + (wn * 32 + tn * 16) * 40 + ks * 16, 40);
            }
#pragma unroll
            for (int tm = 0; tm < 2; tm++)
#pragma unroll
                for (int tn = 0; tn < 2; tn++) {
                    wmma::mma_sync(acc[tm][tn], ah[tm], bh[tn], acc[tm][tn]);
                    wmma::mma_sync(acc[tm][tn], ah[tm], bl[tn], acc[tm][tn]);
                    wmma::mma_sync(acc[tm][tn], al[tm], bh[tn], acc[tm][tn]);
                }
        }
        __syncthreads();   // guard stg^1 overwrite by next iteration's issue
    }

    if (ISQKV) {
#pragma unroll
        for (int tm = 0; tm < 2; tm++)
#pragma unroll
            for (int tn = 0; tn < 2; tn++)
                wmma::store_matrix_sync(C + (size_t)(m0 + wm * 32 + tm * 16) * N + n0 + wn * 32 + tn * 16,
                                        acc[tm][tn], N, wmma::mem_row_major);
    } else {
        // fused bias: stage acc through smem (per-warp 32x36 fp32), add bias
        float* stgf = (float*)sdyn;
        float* ws = stgf + wid * 1152;            // 8 warps x 1152 = 36864 B
#pragma unroll
        for (int tm = 0; tm < 2; tm++)
#pragma unroll
            for (int tn = 0; tn < 2; tn++)
                wmma::store_matrix_sync(ws + tm * 16 * 36 + tn * 16, acc[tm][tn], 36,
                                        wmma::mem_row_major);
        __syncwarp();
        const int m = m0 + wm * 32 + lane;
        const float4* b4 = (const float4*)(bias + n0 + wn * 32);
        float4* dst = (float4*)(C + (size_t)m * N + n0 + wn * 32);
#pragma unroll
        for (int q = 0; q < 8; q++) {
            float4 v = *(float4*)&ws[lane * 36 + q * 4];
            float4 bb = b4[q];
            v.x += bb.x; v.y += bb.y; v.z += bb.z; v.w += bb.w;
            dst[q] = v;
        }
    }
#undef ISSUE_TILE
}

// ---------------------------------------------------------------------------
// Attention: one block per instance (8192). Conflict-free smem layout.
// ---------------------------------------------------------------------------
__global__ __launch_bounds__(256) void attn_kernel()
{
    __shared__ float sQ[32][68];
    __shared__ float sKT[64][36];
    __shared__ float sV[32][68];
    __shared__ float S[32 * 33];

    const int inst = blockIdx.x;
    const int d2 = inst & 15;
    const int c2 = (inst >> 4) & 15;
    const int h  = (inst >> 8) & 7;
    const int b  = inst >> 11;
    const int c  = 2 * h + (c2 >> 3);
    const int d  = 2 * (c2 & 7) + (d2 >> 3);
    const int wb = 4 * (d2 & 7);
    const size_t rowIdx  = (((size_t)(b * 16 + c) * 16 + d) * 32 + wb);
    const size_t srcBase = rowIdx * 1536;
    const size_t dstBase = rowIdx * 512;

    const int tid = threadIdx.x;
    const float4* src4 = (const float4*)(g_qkv + srcBase);

#pragma unroll
    for (int it = 0; it < 6; it++) {
        int p = tid + it * 256;
        float4 v = src4[p];
        int r  = p / 384;
        int f  = p - r * 384;
        int o  = f / 48;
        int t4 = f - o * 48;
        int sec = t4 >> 4;         // 0=Q 1=K 2=V
        int e   = (t4 & 15) * 4;
        int w2  = r * 8 + o;
        if (sec == 0)      *(float4*)&sQ[w2][e] = v;
        else if (sec == 2) *(float4*)&sV[w2][e] = v;
        else {
            sKT[e + 0][w2] = v.x;
            sKT[e + 1][w2] = v.y;
            sKT[e + 2][w2] = v.z;
            sKT[e + 3][w2] = v.w;
        }
    }
    __syncthreads();

    {
        const int i  = tid >> 3;
        const int jg = (tid & 7) * 4;
        const float* qr = sQ[i];
        float s0 = 0.f, s1 = 0.f, s2 = 0.f, s3 = 0.f;
#pragma unroll
        for (int e4 = 0; e4 < 64; e4 += 4) {
            float4 q4 = *(const float4*)(qr + e4);
            float4 ka = *(const float4*)&sKT[e4 + 0][jg];
            float4 kb = *(const float4*)&sKT[e4 + 1][jg];
            float4 kc = *(const float4*)&sKT[e4 + 2][jg];
            float4 kd = *(const float4*)&sKT[e4 + 3][jg];
            s0 = fmaf(q4.x, ka.x, s0); s1 = fmaf(q4.x, ka.y, s1);
            s2 = fmaf(q4.x, ka.z, s2); s3 = fmaf(q4.x, ka.w, s3);
            s0 = fmaf(q4.y, kb.x, s0); s1 = fmaf(q4.y, kb.y, s1);
            s2 = fmaf(q4.y, kb.z, s2); s3 = fmaf(q4.y, kb.w, s3);
            s0 = fmaf(q4.z, kc.x, s0); s1 = fmaf(q4.z, kc.y, s1);
            s2 = fmaf(q4.z, kc.z, s2); s3 = fmaf(q4.z, kc.w, s3);
            s0 = fmaf(q4.w, kd.x, s0); s1 = fmaf(q4.w, kd.y, s1);
            s2 = fmaf(q4.w, kd.z, s2); s3 = fmaf(q4.w, kd.w, s3);
        }
        S[i * 33 + jg + 0] = s0 * 8.0f;
        S[i * 33 + jg + 1] = s1 * 8.0f;
        S[i * 33 + jg + 2] = s2 * 8.0f;
        S[i * 33 + jg + 3] = s3 * 8.0f;
    }
    __syncthreads();

    {
        const int warp = tid >> 5, lane = tid & 31;
#pragma unroll
        for (int r = 0; r < 4; r++) {
            int i = warp * 4 + r;
            float v = S[i * 33 + lane];
            float m = v;
#pragma unroll
            for (int o = 16; o; o >>= 1) m = fmaxf(m, __shfl_xor_sync(0xffffffffu, m, o));
            float p = __expf(v - m);
            float s = p;
#pragma unroll
            for (int o = 16; o; o >>= 1) s += __shfl_xor_sync(0xffffffffu, s, o);
            S[i * 33 + lane] = p * __frcp_rn(s);
        }
    }
    __syncthreads();

    {
        const int i  = tid >> 3;
        const int eg = (tid & 7) * 8;
        float acc[8] = {0.f,0.f,0.f,0.f,0.f,0.f,0.f,0.f};
#pragma unroll
        for (int j = 0; j < 32; j++) {
            float a = S[i * 33 + j];
            float4 v0 = *(const float4*)&sV[j][eg];
            float4 v1 = *(const float4*)&sV[j][eg + 4];
            acc[0] += a*v0.x; acc[1] += a*v0.y; acc[2] += a*v0.z; acc[3] += a*v0.w;
            acc[4] += a*v1.x; acc[5] += a*v1.y; acc[6] += a*v1.z; acc[7] += a*v1.w;
        }
        __align__(16) unsigned short h8[8], l8[8];
#pragma unroll
        for (int q = 0; q < 8; q++) bfsplit(acc[q], h8[q], l8[q]);
        size_t o = dstBase + (size_t)(i >> 3) * 512 + (i & 7) * 64 + eg;
        *(uint4*)(g_vhhi + o) = *(uint4*)h8;
        *(uint4*)(g_vhlo + o) = *(uint4*)l8;
    }
}

// ---------------------------------------------------------------------------
extern "C" void kernel_launch(void* const* d_in, const int* in_sizes, int n_in,
                              void* d_out, int out_size)
{
    if (n_in < 6) return;
    int used[32];
    for (int i = 0; i < 32; i++) used[i] = 0;
    int big[3] = {-1, -1, -1};
    for (int r = 0; r < 3; r++) {
        int best = -1; long long bs = -1;
        for (int i = 0; i < n_in && i < 32; i++) {
            if (used[i]) continue;
            if ((long long)in_sizes[i] > bs) { bs = (long long)in_sizes[i]; best = i; }
        }
        if (best < 0) return;
        big[r] = best; used[best] = 1;
    }
    const float* x     = (const float*)d_in[big[0]];
    const float* W_qkv = (const float*)d_in[big[1]];
    const float* W_out = (const float*)d_in[big[2]];
    const float* vecs[3] = {nullptr, nullptr, nullptr};
    int nv = 0;
    for (int i = 0; i < n_in && i < 32; i++)
        if (!used[i] && nv < 3) vecs[nv++] = (const float*)d_in[i];
    if (nv < 3 || !x || !W_qkv || !W_out) return;

    const float* gamma = vecs[0];
    const float* beta  = vecs[1];
    const float* b_out = vecs[2];
    float* out = (float*)d_out;

    const int GSM = 61440;   // 2 stages x 30KB
    cudaFuncSetAttribute(wmma_gemm_kernel<true>,  cudaFuncAttributeMaxDynamicSharedMemorySize, GSM);
    cudaFuncSetAttribute(wmma_gemm_kernel<false>, cudaFuncAttributeMaxDynamicSharedMemorySize, GSM);

    prep_kernel<<<5120, 256>>>(x, gamma, beta, W_qkv, W_out);
    wmma_gemm_kernel<true><<<dim3(NQKV / 64, NROWS / 128), 256, GSM>>>(nullptr, nullptr);
    attn_kernel<<<NINST, 256>>>();
    wmma_gemm_kernel<false><<<dim3(KDIM / 64, NROWS / 128), 256, GSM>>>(b_out, out);
}

// round 16
// speedup vs baseline: 1.3385x; 1.2902x over previous
#include <cuda_runtime.h>
#include <cuda_bf16.h>
#include <cstdint>

#define NROWS 32768
#define KDIM  512
#define NQKV  1536
#define NINST 8192

// ---------------- device scratch (referenced ONLY in device code) ----------
__device__ __align__(16) float          g_qkv[(size_t)NROWS * NQKV];
__device__ __align__(16) unsigned short g_xnhi[(size_t)NROWS * KDIM];
__device__ __align__(16) unsigned short g_xnlo[(size_t)NROWS * KDIM];
__device__ __align__(16) unsigned short g_vhhi[(size_t)NROWS * KDIM];
__device__ __align__(16) unsigned short g_vhlo[(size_t)NROWS * KDIM];
__device__ __align__(16) unsigned short g_wqhi[(size_t)NQKV * KDIM];   // W_qkv^T [N][K]
__device__ __align__(16) unsigned short g_wqlo[(size_t)NQKV * KDIM];
__device__ __align__(16) unsigned short g_wohi[(size_t)KDIM * KDIM];   // W_out^T [N][K]
__device__ __align__(16) unsigned short g_wolo[(size_t)KDIM * KDIM];

__device__ __forceinline__ void bfsplit(float v, unsigned short& hi, unsigned short& lo) {
    __nv_bfloat16 h = __float2bfloat16(v);
    float r = v - __bfloat162float(h);
    __nv_bfloat16 l = __float2bfloat16(r);
    hi = __bfloat16_as_ushort(h);
    lo = __bfloat16_as_ushort(l);
}

__device__ __forceinline__ uint32_t smem_u32(const void* p) {
    uint32_t a;
    asm("{ .reg .u64 t; cvta.to.shared.u64 t, %1; cvt.u32.u64 %0, t; }" : "=r"(a) : "l"(p));
    return a;
}
__device__ __forceinline__ void cp16(uint32_t saddr, const void* g) {
    asm volatile("cp.async.cg.shared.global [%0], [%1], 16;" :: "r"(saddr), "l"(g));
}
__device__ __forceinline__ void ldsm_x4(uint32_t* r, uint32_t addr) {
    asm volatile("ldmatrix.sync.aligned.m8n8.x4.shared.b16 {%0,%1,%2,%3}, [%4];"
                 : "=r"(r[0]), "=r"(r[1]), "=r"(r[2]), "=r"(r[3]) : "r"(addr));
}
__device__ __forceinline__ void mma16816(float* c, const uint32_t* a, uint32_t b0, uint32_t b1) {
    asm volatile("mma.sync.aligned.m16n8k16.row.col.f32.bf16.bf16.f32 "
                 "{%0,%1,%2,%3}, {%4,%5,%6,%7}, {%8,%9}, {%0,%1,%2,%3};"
                 : "+f"(c[0]), "+f"(c[1]), "+f"(c[2]), "+f"(c[3])
                 : "r"(a[0]), "r"(a[1]), "r"(a[2]), "r"(a[3]), "r"(b0), "r"(b1));
}

// ---------------------------------------------------------------------------
// Prep kernel: LN (blocks 0..4095) + W_qkv split (4096..4863) + W_out split
// (4864..5119).
// ---------------------------------------------------------------------------
__global__ __launch_bounds__(256) void prep_kernel(const float* __restrict__ x,
                                                   const float* __restrict__ gamma,
                                                   const float* __restrict__ beta,
                                                   const float* __restrict__ Wq,
                                                   const float* __restrict__ Wo)
{
    __shared__ float t[32][33];
    const int nb = blockIdx.x;

    if (nb < 4096) {
        int row  = (nb * 256 + threadIdx.x) >> 5;
        int lane = threadIdx.x & 31;

        const float4* xr = (const float4*)(x + (size_t)row * KDIM);
        float4 v[4];
        float s = 0.f, ss = 0.f;
#pragma unroll
        for (int i = 0; i < 4; i++) {
            v[i] = xr[lane + i * 32];
            s  += v[i].x + v[i].y + v[i].z + v[i].w;
            ss += v[i].x * v[i].x + v[i].y * v[i].y + v[i].z * v[i].z + v[i].w * v[i].w;
        }
#pragma unroll
        for (int o = 16; o; o >>= 1) {
            s  += __shfl_xor_sync(0xffffffffu, s, o);
            ss += __shfl_xor_sync(0xffffffffu, ss, o);
        }
        float mean = s * (1.0f / KDIM);
        float inv  = rsqrtf(ss * (1.0f / KDIM) - mean * mean + 1e-5f);

        const float4* g4 = (const float4*)gamma;
        const float4* b4 = (const float4*)beta;
#pragma unroll
        for (int i = 0; i < 4; i++) {
            int idx = lane + i * 32;
            float4 g = g4[idx], b = b4[idx], r;
            r.x = (v[i].x - mean) * inv * g.x + b.x;
            r.y = (v[i].y - mean) * inv * g.y + b.y;
            r.z = (v[i].z - mean) * inv * g.z + b.z;
            r.w = (v[i].w - mean) * inv * g.w + b.w;
            __align__(8) unsigned short h4[4], l4[4];
            bfsplit(r.x, h4[0], l4[0]); bfsplit(r.y, h4[1], l4[1]);
            bfsplit(r.z, h4[2], l4[2]); bfsplit(r.w, h4[3], l4[3]);
            size_t e = (size_t)row * KDIM + idx * 4;
            *(uint2*)(g_xnhi + e) = *(uint2*)h4;
            *(uint2*)(g_xnlo + e) = *(uint2*)l4;
        }
    } else {
        const bool isq = nb < 4864;
        const int tix  = isq ? (nb - 4096) : (nb - 4864);
        const int NBX  = isq ? 48 : 16;
        const int bx = tix % NBX, by = tix / NBX;
        const float* W = isq ? Wq : Wo;
        unsigned short* Thi = isq ? g_wqhi : g_wohi;
        unsigned short* Tlo = isq ? g_wqlo : g_wolo;
        const int N = isq ? NQKV : KDIM;

        int xo = bx * 32, yo = by * 32;
        int tx = threadIdx.x & 31, ty = threadIdx.x >> 5;
#pragma unroll
        for (int j = 0; j < 4; j++)
            t[ty + 8 * j][tx] = W[(size_t)(yo + ty + 8 * j) * N + xo + tx];
        __syncthreads();
#pragma unroll
        for (int j = 0; j < 4; j++) {
            float v = t[tx][ty + 8 * j];
            int n = xo + ty + 8 * j, k = yo + tx;
            unsigned short hi, lo;
            bfsplit(v, hi, lo);
            Thi[(size_t)n * KDIM + k] = hi;
            Tlo[(size_t)n * KDIM + k] = lo;
        }
    }
}

// ---------------------------------------------------------------------------
// RAW mma.sync bf16 split GEMM (R15: tensor pipe only 41% ACTIVE with 2 CTAs
// resident -> stall is intra-warp LDSM->HMMA serialization that wmma's opaque
// fragments prevent fixing). Explicit ldmatrix + mma.sync with fragment
// double-buffering: LDSM of stage F1 issues before the 24 HMMA of F0, etc.
// Block 128x64, BK=32, 8 warps (4x2), warp tile 32x32, 2-stage cp.async,
// smem 60KB -> 2 CTAs/SM. Stride 40 bf16 = 80B (conflict-free LDSM).
// !ISQKV adds bias directly in the register epilogue.
// ---------------------------------------------------------------------------
template<bool ISQKV>
__global__ __launch_bounds__(256, 2) void mma_gemm_kernel(const float* __restrict__ bias,
                                                          float* __restrict__ Cout)
{
    extern __shared__ __align__(16) __nv_bfloat16 sdyn[];
    // stage base (elements) = stg*15360:
    //   Ahi +0 (128x40), Alo +5120, Bhi +10240 (64x40), Blo +12800

    const int N = ISQKV ? NQKV : KDIM;
    const unsigned short* pA[2] = { ISQKV ? g_xnhi : g_vhhi, ISQKV ? g_xnlo : g_vhlo };
    const unsigned short* pB[2] = { ISQKV ? g_wqhi : g_wohi, ISQKV ? g_wqlo : g_wolo };
    float* C = ISQKV ? g_qkv : Cout;

    const int tid = threadIdx.x, wid = tid >> 5, lane = tid & 31;
    const int wm = wid >> 1;            // 0..3 -> m offset 32*wm
    const int wn = wid & 1;             // 0..1 -> n offset 32*wn
    const int m0 = blockIdx.y * 128, n0 = blockIdx.x * 64;
    const uint32_t sb = smem_u32(sdyn);

    // ldmatrix per-lane element offsets within a split region
    // A (16x16 tile at (wm*32 + mt*16, ks*16)): lanes 0-15 rows, 16-31 rows @k+8
    const int a_eoff = (wm * 32 + (lane & 15)) * 40 + ((lane >> 4) << 3);
    // B (n16 x k16 tile): lanes 0-7 n-rows@k0, 8-15 same@k8, 16-23 n+8@k0, 24-31 n+8@k8
    const int b_eoff = (wn * 32 + ((lane >> 4) << 3) + (lane & 7)) * 40 + (((lane >> 3) & 1) << 3);

    const uint32_t aAddr0 = sb + 2u * (0     + a_eoff);
    const uint32_t aAddr1 = sb + 2u * (5120  + a_eoff);
    const uint32_t bAddr0 = sb + 2u * (10240 + b_eoff);
    const uint32_t bAddr1 = sb + 2u * (12800 + b_eoff);

    float acc[2][4][4];
#pragma unroll
    for (int i = 0; i < 2; i++)
#pragma unroll
        for (int j = 0; j < 4; j++)
#pragma unroll
            for (int q = 0; q < 4; q++) acc[i][j][q] = 0.f;

#define ISSUE_TILE(KT, STG) do { \
    const int _k0 = (KT) * 32; \
    _Pragma("unroll") \
    for (int t = 0; t < 6; t++) { \
        int cid = tid + t * 256; \
        if (cid < 1024) { \
            int s = cid >> 9, r = (cid >> 2) & 127, kc = cid & 3; \
            uint32_t dst = sb + (uint32_t)(((STG) * 15360 + s * 5120 + r * 40 + kc * 8) * 2); \
            cp16(dst, pA[s] + (size_t)(m0 + r) * KDIM + _k0 + kc * 8); \
        } else { \
            int c = cid - 1024; \
            int s = c >> 8, r = (c >> 2) & 63, kc = c & 3; \
            uint32_t dst = sb + (uint32_t)(((STG) * 15360 + 10240 + s * 2560 + r * 40 + kc * 8) * 2); \
            cp16(dst, pB[s] + (size_t)(n0 + r) * KDIM + _k0 + kc * 8); \
        } \
    } \
    asm volatile("cp.async.commit_group;"); \
} while (0)

    // fragment buffers: [split][mt or half][4]
    uint32_t fa0[2][2][4], fb0[2][2][4];
    uint32_t fa1[2][2][4], fb1[2][2][4];

#define LOADF(FA, FB, STG, KS) do { \
    const uint32_t _o = 2u * ((STG) * 15360 + (KS) * 16); \
    _Pragma("unroll") \
    for (int mt = 0; mt < 2; mt++) { \
        ldsm_x4(FA[0][mt], aAddr0 + _o + 2u * (mt * 640)); \
        ldsm_x4(FA[1][mt], aAddr1 + _o + 2u * (mt * 640)); \
    } \
    _Pragma("unroll") \
    for (int hf = 0; hf < 2; hf++) { \
        ldsm_x4(FB[0][hf], bAddr0 + _o + 2u * (hf * 640)); \
        ldsm_x4(FB[1][hf], bAddr1 + _o + 2u * (hf * 640)); \
    } \
} while (0)

#define DOMMA(FA, FB) do { \
    _Pragma("unroll") \
    for (int mt = 0; mt < 2; mt++) \
        _Pragma("unroll") \
        for (int j = 0; j < 4; j++) { \
            const int hf = j >> 1, sub = j & 1; \
            float* cc = acc[mt][j]; \
            mma16816(cc, FA[0][mt], FB[0][hf][sub * 2], FB[0][hf][sub * 2 + 1]); \
            mma16816(cc, FA[0][mt], FB[1][hf][sub * 2], FB[1][hf][sub * 2 + 1]); \
            mma16816(cc, FA[1][mt], FB[0][hf][sub * 2], FB[0][hf][sub * 2 + 1]); \
        } \
} while (0)

    ISSUE_TILE(0, 0);
    asm volatile("cp.async.wait_group 0;" ::: "memory");
    __syncthreads();
    LOADF(fa0, fb0, 0, 0);

#pragma unroll 1
    for (int kt = 0; kt < 16; kt++) {
        const int stg = kt & 1;
        LOADF(fa1, fb1, stg, 1);            // LDSM hides under DOMMA(F0)
        if (kt < 15) ISSUE_TILE(kt + 1, stg ^ 1);
        DOMMA(fa0, fb0);
        if (kt < 15) {
            asm volatile("cp.async.wait_group 0;" ::: "memory");
            __syncthreads();                 // stage stg fully consumed (regs)
            LOADF(fa0, fb0, stg ^ 1, 0);     // LDSM hides under DOMMA(F1)
        }
        DOMMA(fa1, fb1);
    }

    // epilogue: c-frag rows lane>>2 (+8), cols (lane&3)*2 within n8 tile j
#pragma unroll
    for (int mt = 0; mt < 2; mt++) {
        const int m = m0 + wm * 32 + mt * 16 + (lane >> 2);
#pragma unroll
        for (int j = 0; j < 4; j++) {
            const int col = n0 + wn * 32 + j * 8 + (lane & 3) * 2;
            float b0 = 0.f, b1 = 0.f;
            if (!ISQKV) { b0 = __ldg(bias + col); b1 = __ldg(bias + col + 1); }
            *(float2*)(C + (size_t)m * N + col)       = make_float2(acc[mt][j][0] + b0, acc[mt][j][1] + b1);
            *(float2*)(C + (size_t)(m + 8) * N + col) = make_float2(acc[mt][j][2] + b0, acc[mt][j][3] + b1);
        }
    }
#undef ISSUE_TILE
#undef LOADF
#undef DOMMA
}

// ---------------------------------------------------------------------------
// Attention: one block per instance (8192). Conflict-free smem layout.
// ---------------------------------------------------------------------------
__global__ __launch_bounds__(256) void attn_kernel()
{
    __shared__ float sQ[32][68];
    __shared__ float sKT[64][36];
    __shared__ float sV[32][68];
    __shared__ float S[32 * 33];

    const int inst = blockIdx.x;
    const int d2 = inst & 15;
    const int c2 = (inst >> 4) & 15;
    const int h  = (inst >> 8) & 7;
    const int b  = inst >> 11;
    const int c  = 2 * h + (c2 >> 3);
    const int d  = 2 * (c2 & 7) + (d2 >> 3);
    const int wb = 4 * (d2 & 7);
    const size_t rowIdx  = (((size_t)(b * 16 + c) * 16 + d) * 32 + wb);
    const size_t srcBase = rowIdx * 1536;
    const size_t dstBase = rowIdx * 512;

    const int tid = threadIdx.x;
    const float4* src4 = (const float4*)(g_qkv + srcBase);

#pragma unroll
    for (int it = 0; it < 6; it++) {
        int p = tid + it * 256;
        float4 v = src4[p];
        int r  = p / 384;
        int f  = p - r * 384;
        int o  = f / 48;
        int t4 = f - o * 48;
        int sec = t4 >> 4;         // 0=Q 1=K 2=V
        int e   = (t4 & 15) * 4;
        int w2  = r * 8 + o;
        if (sec == 0)      *(float4*)&sQ[w2][e] = v;
        else if (sec == 2) *(float4*)&sV[w2][e] = v;
        else {
            sKT[e + 0][w2] = v.x;
            sKT[e + 1][w2] = v.y;
            sKT[e + 2][w2] = v.z;
            sKT[e + 3][w2] = v.w;
        }
    }
    __syncthreads();

    {
        const int i  = tid >> 3;
        const int jg = (tid & 7) * 4;
        const float* qr = sQ[i];
        float s0 = 0.f, s1 = 0.f, s2 = 0.f, s3 = 0.f;
#pragma unroll
        for (int e4 = 0; e4 < 64; e4 += 4) {
            float4 q4 = *(const float4*)(qr + e4);
            float4 ka = *(const float4*)&sKT[e4 + 0][jg];
            float4 kb = *(const float4*)&sKT[e4 + 1][jg];
            float4 kc = *(const float4*)&sKT[e4 + 2][jg];
            float4 kd = *(const float4*)&sKT[e4 + 3][jg];
            s0 = fmaf(q4.x, ka.x, s0); s1 = fmaf(q4.x, ka.y, s1);
            s2 = fmaf(q4.x, ka.z, s2); s3 = fmaf(q4.x, ka.w, s3);
            s0 = fmaf(q4.y, kb.x, s0); s1 = fmaf(q4.y, kb.y, s1);
            s2 = fmaf(q4.y, kb.z, s2); s3 = fmaf(q4.y, kb.w, s3);
            s0 = fmaf(q4.z, kc.x, s0); s1 = fmaf(q4.z, kc.y, s1);
            s2 = fmaf(q4.z, kc.z, s2); s3 = fmaf(q4.z, kc.w, s3);
            s0 = fmaf(q4.w, kd.x, s0); s1 = fmaf(q4.w, kd.y, s1);
            s2 = fmaf(q4.w, kd.z, s2); s3 = fmaf(q4.w, kd.w, s3);
        }
        S[i * 33 + jg + 0] = s0 * 8.0f;
        S[i * 33 + jg + 1] = s1 * 8.0f;
        S[i * 33 + jg + 2] = s2 * 8.0f;
        S[i * 33 + jg + 3] = s3 * 8.0f;
    }
    __syncthreads();

    {
        const int warp = tid >> 5, lane = tid & 31;
#pragma unroll
        for (int r = 0; r < 4; r++) {
            int i = warp * 4 + r;
            float v = S[i * 33 + lane];
            float m = v;
#pragma unroll
            for (int o = 16; o; o >>= 1) m = fmaxf(m, __shfl_xor_sync(0xffffffffu, m, o));
            float p = __expf(v - m);
            float s = p;
#pragma unroll
            for (int o = 16; o; o >>= 1) s += __shfl_xor_sync(0xffffffffu, s, o);
            S[i * 33 + lane] = p * __frcp_rn(s);
        }
    }
    __syncthreads();

    {
        const int i  = tid >> 3;
        const int eg = (tid & 7) * 8;
        float acc[8] = {0.f,0.f,0.f,0.f,0.f,0.f,0.f,0.f};
#pragma unroll
        for (int j = 0; j < 32; j++) {
            float a = S[i * 33 + j];
            float4 v0 = *(const float4*)&sV[j][eg];
            float4 v1 = *(const float4*)&sV[j][eg + 4];
            acc[0] += a*v0.x; acc[1] += a*v0.y; acc[2] += a*v0.z; acc[3] += a*v0.w;
            acc[4] += a*v1.x; acc[5] += a*v1.y; acc[6] += a*v1.z; acc[7] += a*v1.w;
        }
        __align__(16) unsigned short h8[8], l8[8];
#pragma unroll
        for (int q = 0; q < 8; q++) bfsplit(acc[q], h8[q], l8[q]);
        size_t o = dstBase + (size_t)(i >> 3) * 512 + (i & 7) * 64 + eg;
        *(uint4*)(g_vhhi + o) = *(uint4*)h8;
        *(uint4*)(g_vhlo + o) = *(uint4*)l8;
    }
}

// ---------------------------------------------------------------------------
extern "C" void kernel_launch(void* const* d_in, const int* in_sizes, int n_in,
                              void* d_out, int out_size)
{
    if (n_in < 6) return;
    int used[32];
    for (int i = 0; i < 32; i++) used[i] = 0;
    int big[3] = {-1, -1, -1};
    for (int r = 0; r < 3; r++) {
        int best = -1; long long bs = -1;
        for (int i = 0; i < n_in && i < 32; i++) {
            if (used[i]) continue;
            if ((long long)in_sizes[i] > bs) { bs = (long long)in_sizes[i]; best = i; }
        }
        if (best < 0) return;
        big[r] = best; used[best] = 1;
    }
    const float* x     = (const float*)d_in[big[0]];
    const float* W_qkv = (const float*)d_in[big[1]];
    const float* W_out = (const float*)d_in[big[2]];
    const float* vecs[3] = {nullptr, nullptr, nullptr};
    int nv = 0;
    for (int i = 0; i < n_in && i < 32; i++)
        if (!used[i] && nv < 3) vecs[nv++] = (const float*)d_in[i];
    if (nv < 3 || !x || !W_qkv || !W_out) return;

    const float* gamma = vecs[0];
    const float* beta  = vecs[1];
    const float* b_out = vecs[2];
    float* out = (float*)d_out;

    const int GSM = 61440;   // 2 stages x 30KB
    cudaFuncSetAttribute(mma_gemm_kernel<true>,  cudaFuncAttributeMaxDynamicSharedMemorySize, GSM);
    cudaFuncSetAttribute(mma_gemm_kernel<false>, cudaFuncAttributeMaxDynamicSharedMemorySize, GSM);

    prep_kernel<<<5120, 256>>>(x, gamma, beta, W_qkv, W_out);
    mma_gemm_kernel<true><<<dim3(NQKV / 64, NROWS / 128), 256, GSM>>>(nullptr, nullptr);
    attn_kernel<<<NINST, 256>>>();
    mma_gemm_kernel<false><<<dim3(KDIM / 64, NROWS / 128), 256, GSM>>>(b_out, out);
}